// round 13
// baseline (speedup 1.0000x reference)
#include <cuda_runtime.h>

// ClosebyValuationFunction:
//   out[i] = (|z1[i,4]-z2[i,4]| < 2.0 && |z1[i,5]-z2[i,5]| <= 0.1) ? 0.99 : 0.01
//
// Winning access pattern (R2..R12 sweep): per-thread gathered float2 of
// (col4,col5) at float2 index 3i+2 — 24 B lane stride, the finest grain,
// measured 82-84% DRAM / ~6.8 TB/s. Coarser restructures all regressed.
//
// R12 change: single-wave persistent grid-stride launch. Old grid
// (32768 CTAs, ~27 waves) pays repeated wave transitions + per-wave CTA
// tail imbalance. One full-residency wave (1184 CTAs = ~148 SMs x 8)
// loops over rows with the whole-grid stride, unrolled x2 for MLP=4
// while keeping adjacent threads on adjacent rows.

constexpr int BLOCK = 256;
constexpr int GRID_PERSIST = 148 * 8;   // one full residency wave

__global__ __launch_bounds__(BLOCK)
void closeby_persist_kernel(const float2* __restrict__ z1,
                            const float2* __restrict__ z2,
                            float* __restrict__ out,
                            int n)
{
    const int stride = gridDim.x * blockDim.x;
    int i = blockIdx.x * blockDim.x + threadIdx.x;

    // Unrolled x2: two independent row groups in flight (4 loads).
    for (; i + stride < n; i += 2 * stride) {
        int j = i + stride;
        int idx0 = 3 * i + 2;
        int idx1 = 3 * j + 2;
        float2 a0 = __ldcs(&z1[idx0]);
        float2 b0 = __ldcs(&z2[idx0]);
        float2 a1 = __ldcs(&z1[idx1]);
        float2 b1 = __ldcs(&z2[idx1]);
        bool c0 = (fabsf(a0.x - b0.x) < 2.0f) & (fabsf(a0.y - b0.y) <= 0.1f);
        bool c1 = (fabsf(a1.x - b1.x) < 2.0f) & (fabsf(a1.y - b1.y) <= 0.1f);
        __stcs(&out[i], c0 ? 0.99f : 0.01f);
        __stcs(&out[j], c1 ? 0.99f : 0.01f);
    }
    // Remainder (at most one iteration per thread).
    if (i < n) {
        int idx = 3 * i + 2;
        float2 a = __ldcs(&z1[idx]);
        float2 b = __ldcs(&z2[idx]);
        bool c = (fabsf(a.x - b.x) < 2.0f) & (fabsf(a.y - b.y) <= 0.1f);
        __stcs(&out[i], c ? 0.99f : 0.01f);
    }
}

extern "C" void kernel_launch(void* const* d_in, const int* in_sizes, int n_in,
                              void* d_out, int out_size)
{
    const float2* z1 = (const float2*)d_in[0];
    const float2* z2 = (const float2*)d_in[1];
    float* out = (float*)d_out;
    int n = out_size;                   // B rows (= in_sizes[0] / 6)

    closeby_persist_kernel<<<GRID_PERSIST, BLOCK>>>(z1, z2, out, n);
}

// round 16
// speedup vs baseline: 1.0547x; 1.0547x over previous
#include <cuda_runtime.h>

// ClosebyValuationFunction (FINAL — R7 configuration, best measured):
//   out[i] = (|z1[i,4]-z2[i,4]| < 2.0 && |z1[i,5]-z2[i,5]| <= 0.1) ? 0.99 : 0.01
//
// Flat launch, one row per thread, gathered float2 of (col4,col5) at
// float2 index 3i+2. DRAM traffic is at the irreducible 436 MB floor
// (24 B rows; lcm(24,32)=96 B periods touch all 3 sectors — the full
// inputs must stream no matter the pattern). Full sweep R2..R13:
//   flat 1-row gather (this):     82.0-83.5% DRAM, 62.5-64.3 us  <- best
//   2 rows/thread:                82.2%, 63.0 us
//   4 rows/thread float4:         78.0%, 66.6 us
//   SMEM-staged coalesced:        78.0%, 64.3 us
//   persistent grid-stride x2:    79.0%, 65.6 us
// Achieved ~6.8 TB/s = 85% of spec = the chip's practical ceiling for a
// 2-read+1-write mixed stream; compute pipes <5%, nothing SM-side binds.

__global__ __launch_bounds__(256)
void closeby_kernel(const float2* __restrict__ z1,
                    const float2* __restrict__ z2,
                    float* __restrict__ out,
                    int n)
{
    int i = blockIdx.x * blockDim.x + threadIdx.x;
    if (i < n) {
        int idx = 3 * i + 2;            // float2 index of (col4, col5) in row i
        float2 a = __ldcs(&z1[idx]);
        float2 b = __ldcs(&z2[idx]);
        float dx = fabsf(a.x - b.x);
        float dy = fabsf(a.y - b.y);
        bool close = (dx < 2.0f) & (dy <= 0.1f);
        __stcs(&out[i], close ? 0.99f : 0.01f);
    }
}

extern "C" void kernel_launch(void* const* d_in, const int* in_sizes, int n_in,
                              void* d_out, int out_size)
{
    const float2* z1 = (const float2*)d_in[0];
    const float2* z2 = (const float2*)d_in[1];
    float* out = (float*)d_out;
    int n = out_size;                   // B rows (= in_sizes[0] / 6)

    int threads = 256;
    int blocks = (n + threads - 1) / threads;
    closeby_kernel<<<blocks, threads>>>(z1, z2, out, n);
}

// round 17
// speedup vs baseline: 1.0552x; 1.0005x over previous
#include <cuda_runtime.h>

// ClosebyValuationFunction — terminal access pattern, block-size experiment:
//   out[i] = (|z1[i,4]-z2[i,4]| < 2.0 && |z1[i,5]-z2[i,5]| <= 0.1) ? 0.99 : 0.01
//
// Flat launch, one row per thread, gathered float2 of (col4,col5) at
// float2 index 3i+2 — the measured-best pattern (82-83.5% DRAM, ~6.8 TB/s;
// all restructures R4/R6/R9/R13 regressed to 78-82%). Traffic is at the
// irreducible 436 MB floor. Only never-tested knob left: block size.
// 512 threads/block halves the CTA count (16384 CTAs) — fewer per-wave
// scheduling events and coarser CTA-tail granularity at identical warp
// occupancy (4 CTAs x 16 warps = 64 warps/SM). Expected neutral-to-+1%.

__global__ __launch_bounds__(512)
void closeby_kernel(const float2* __restrict__ z1,
                    const float2* __restrict__ z2,
                    float* __restrict__ out,
                    int n)
{
    int i = blockIdx.x * blockDim.x + threadIdx.x;
    if (i < n) {
        int idx = 3 * i + 2;            // float2 index of (col4, col5) in row i
        float2 a = __ldcs(&z1[idx]);
        float2 b = __ldcs(&z2[idx]);
        float dx = fabsf(a.x - b.x);
        float dy = fabsf(a.y - b.y);
        bool close = (dx < 2.0f) & (dy <= 0.1f);
        __stcs(&out[i], close ? 0.99f : 0.01f);
    }
}

extern "C" void kernel_launch(void* const* d_in, const int* in_sizes, int n_in,
                              void* d_out, int out_size)
{
    const float2* z1 = (const float2*)d_in[0];
    const float2* z2 = (const float2*)d_in[1];
    float* out = (float*)d_out;
    int n = out_size;                   // B rows (= in_sizes[0] / 6)

    int threads = 512;
    int blocks = (n + threads - 1) / threads;
    closeby_kernel<<<blocks, threads>>>(z1, z2, out, n);
}